// round 6
// baseline (speedup 1.0000x reference)
#include <cuda_runtime.h>
#include <cuda_bf16.h>

#define NBLOCKS 1184          // 148 SMs * 8 CTAs, single wave
#define NTHREADS 256
#define MLP 8                 // independent loads in flight per thread

__device__ float g_partials[NBLOCKS];
__device__ unsigned int g_ticket = 0;   // reset by last block -> graph-replay safe

__global__ __launch_bounds__(NTHREADS)
void sumsq_fused_kernel(const float* __restrict__ w, long nw,
                        const float* __restrict__ b, long nb,
                        float* __restrict__ out) {
    const long nw4 = nw >> 2;
    const long nb4 = nb >> 2;
    const float4* __restrict__ w4 = reinterpret_cast<const float4*>(w);
    const float4* __restrict__ b4 = reinterpret_cast<const float4*>(b);

    // Static contiguous partition: block owns [start, end) of the float4 range.
    const long span  = (nw4 + NBLOCKS - 1) / NBLOCKS;
    const long start = (long)blockIdx.x * span;
    const long end   = min(start + span, nw4);

    float acc[MLP];
    #pragma unroll
    for (int k = 0; k < MLP; k++) acc[k] = 0.0f;

    // Hot loop: 8 independent LDG.128 per thread, covering one contiguous
    // 32KB window per block iteration. No guards in the fast path.
    long i = start + threadIdx.x;
    for (; i + (MLP - 1) * NTHREADS < end; i += MLP * NTHREADS) {
        float4 v[MLP];
        #pragma unroll
        for (int k = 0; k < MLP; k++) v[k] = w4[i + k * NTHREADS];
        #pragma unroll
        for (int k = 0; k < MLP; k++)
            acc[k] += v[k].x * v[k].x + v[k].y * v[k].y
                    + v[k].z * v[k].z + v[k].w * v[k].w;
    }
    // remainder of this block's span
    for (; i < end; i += NTHREADS) {
        float4 v = w4[i];
        acc[0] += v.x * v.x + v.y * v.y + v.z * v.z + v.w * v.w;
    }

    // bias (tiny) + scalar tails: grid-stride
    {
        const long idx    = (long)blockIdx.x * NTHREADS + threadIdx.x;
        const long stride = (long)NBLOCKS * NTHREADS;
        for (long j = idx; j < nb4; j += stride) {
            float4 v = b4[j];
            acc[1] += v.x * v.x + v.y * v.y + v.z * v.z + v.w * v.w;
        }
        for (long j = (nw4 << 2) + idx; j < nw; j += stride) { float v = w[j]; acc[2] += v * v; }
        for (long j = (nb4 << 2) + idx; j < nb; j += stride) { float v = b[j]; acc[3] += v * v; }
    }

    float a = ((acc[0] + acc[1]) + (acc[2] + acc[3]))
            + ((acc[4] + acc[5]) + (acc[6] + acc[7]));

    // warp reduce
    #pragma unroll
    for (int o = 16; o > 0; o >>= 1)
        a += __shfl_xor_sync(0xffffffffu, a, o);

    __shared__ float s[NTHREADS / 32];
    __shared__ bool  is_last;
    if ((threadIdx.x & 31) == 0) s[threadIdx.x >> 5] = a;
    __syncthreads();

    if (threadIdx.x < 32) {
        a = (threadIdx.x < NTHREADS / 32) ? s[threadIdx.x] : 0.0f;
        #pragma unroll
        for (int o = 16; o > 0; o >>= 1)
            a += __shfl_xor_sync(0xffffffffu, a, o);
        if (threadIdx.x == 0) {
            g_partials[blockIdx.x] = a;
            __threadfence();
            unsigned int t = atomicAdd(&g_ticket, 1u);
            is_last = (t == (unsigned int)NBLOCKS - 1u);
        }
    }
    __syncthreads();

    // Last-arriving block: deterministic fixed-order reduce of all partials.
    if (is_last) {
        float f = 0.0f;
        for (int k = threadIdx.x; k < NBLOCKS; k += NTHREADS)
            f += g_partials[k];

        #pragma unroll
        for (int o = 16; o > 0; o >>= 1)
            f += __shfl_xor_sync(0xffffffffu, f, o);

        if ((threadIdx.x & 31) == 0) s[threadIdx.x >> 5] = f;
        __syncthreads();

        if (threadIdx.x < 32) {
            f = (threadIdx.x < NTHREADS / 32) ? s[threadIdx.x] : 0.0f;
            #pragma unroll
            for (int o = 16; o > 0; o >>= 1)
                f += __shfl_xor_sync(0xffffffffu, f, o);
            if (threadIdx.x == 0) {
                out[0] = 0.12f * f;   // (2+4+6)*LAMB; segment sums re-total to full sum
                g_ticket = 0;         // reset for next graph replay
            }
        }
    }
}

extern "C" void kernel_launch(void* const* d_in, const int* in_sizes, int n_in,
                              void* d_out, int out_size) {
    const float* w = (const float*)d_in[0];   // fc_weights
    const float* b = (const float*)d_in[1];   // fc_bias
    // d_in[2] = coarse_map: algebraically irrelevant
    float* out = (float*)d_out;

    long nw = (long)in_sizes[0];
    long nb = (long)in_sizes[1];

    sumsq_fused_kernel<<<NBLOCKS, NTHREADS>>>(w, nw, b, nb, out);
}